// round 16
// baseline (speedup 1.0000x reference)
#include <cuda_runtime.h>
#include <cstdint>

// Problem constants
#define B_   4
#define C_   128
#define H_   192
#define W_   192
#define HW_  (H_*W_)
#define K_   9
#define PAD  4
#define NOFF 81

// Tiling: occ-3, CH=16 (8 barriers), y-only smem, NBUF=3, x via LDG
#define TH   8
#define TW   16
#define PXT  4
#define NTHREADS 288           // 4 wg * 9 io * 8 hr
#define CH   16
#define NSTAGE 8
#define NBUF 3
#define YROWS 16               // TH + 2*PAD
#define YPITCH 48              // ≡16 mod 32 -> conflict-free; 2 channels share one row
#define YSZ  (8*YROWS*YPITCH)  // 6144 floats = 24KB per stage (8 rowsets x 2 col-halves)
#define SMEM_BYTES (NBUF*YSZ*4) // 73728 bytes (3 blocks x 72KB = 216KB <= 228KB)

typedef unsigned long long u64;

__device__ __forceinline__ u64 pack2(float lo, float hi) {
    u64 r;
    asm("mov.b64 %0, {%1, %2};" : "=l"(r) : "f"(lo), "f"(hi));
    return r;
}
__device__ __forceinline__ u64 ffma2u(u64 a, u64 b, u64 c) {
    u64 d;
    asm("fma.rn.f32x2 %0, %1, %2, %3;" : "=l"(d) : "l"(a), "l"(b), "l"(c));
    return d;
}
__device__ __forceinline__ float2 unpack2(u64 v) {
    float2 r;
    asm("mov.b64 {%0, %1}, %2;" : "=f"(r.x), "=f"(r.y) : "l"(v));
    return r;
}

__device__ __forceinline__ void cp16(uint32_t dst, const void* src, int srcsize) {
    asm volatile("cp.async.cg.shared.global [%0], [%1], 16, %2;"
                 :: "r"(dst), "l"(src), "r"(srcsize));
}
__device__ __forceinline__ void cp_commit() {
    asm volatile("cp.async.commit_group;");
}
template <int N>
__device__ __forceinline__ void cp_wait() {
    asm volatile("cp.async.wait_group %0;" :: "n"(N));
}

__global__ void __launch_bounds__(NTHREADS, 3)
corr_kernel(const float* __restrict__ x,
            const float* __restrict__ y,
            float* __restrict__ out) {
    extern __shared__ float sm[];

    const int tid = threadIdx.x;
    const int wg  = tid & 3;
    const int io  = (tid >> 2) % 9;
    const int hr  = tid / 36;

    const int b  = blockIdx.z;
    const int h0 = blockIdx.y * TH;
    const int w0 = blockIdx.x * TW;

    const float* xb = x + (size_t)b * C_ * HW_;
    const float* yb = y + (size_t)b * C_ * HW_;

    const uint32_t sm_base = (uint32_t)__cvta_generic_to_shared(sm);

    // y chunk 0..1535 -> channel c (0..15): rowset (c&7), col-half (c>>3)
    auto y_chunk = [&](int c0, uint32_t ys_base, int chunk) {
        int t = chunk / 6;               // 0..255 -> (c, r)
        int q = chunk - 6 * t;
        int c = t >> 4;                  // 0..15
        int r = t & 15;
        int gh = h0 + r - PAD;
        int gw = w0 - 4 + q * 4;
        bool ok = ((unsigned)gh < (unsigned)H_) &&
                  ((unsigned)gw <= (unsigned)(W_ - 4));
        const float* src = ok ? yb + (size_t)(c0 + c) * HW_ + gh * W_ + gw : yb;
        uint32_t dst = ys_base +
            (uint32_t)(((c & 7) * YROWS + r) * YPITCH + (c >> 3) * 24 + q * 4) * 4u;
        cp16(dst, src, ok ? 16 : 0);
    };

    // half-stage prefetch groups (3 cp / thread each)
    auto prefetchA = [&](int s, int buf) {
        const uint32_t ysb = sm_base + (uint32_t)(buf * YSZ) * 4u;
        if (tid < 256) {
            y_chunk(s * CH, ysb, tid);
            y_chunk(s * CH, ysb, tid + 256);
            y_chunk(s * CH, ysb, tid + 512);
        }
        cp_commit();
    };
    auto prefetchB = [&](int s, int buf) {
        const uint32_t ysb = sm_base + (uint32_t)(buf * YSZ) * 4u;
        if (tid < 256) {
            y_chunk(s * CH, ysb, tid + 768);
            y_chunk(s * CH, ysb, tid + 1024);
            y_chunk(s * CH, ysb, tid + 1280);
        }
        cp_commit();
    };

    // accumulators: acc[j][q], pixel pair (2q, 2q+1); 18 u64 = 36 regs
    u64 acc[K_][2];
#pragma unroll
    for (int j = 0; j < K_; j++) { acc[j][0] = 0ull; acc[j][1] = 0ull; }

    // x: direct LDG.128, depth-2 register pipeline over linear channels 0..127
    const float* xld = xb + (h0 + hr) * W_ + w0 + wg * PXT;
    float4 xq0 = *(const float4*)xld; xld += HW_;    // ch 0
    float4 xq1 = *(const float4*)xld; xld += HW_;    // ch 1; xld -> ch 2

    // 8 channels of one col-half; chbase = global channel of first (= s*16+half*8)
    auto compute_half = [&](int buf, int half, int chbase) {
        const float* yr = sm + buf * YSZ + (hr + io) * YPITCH + half * 24 + wg * PXT;
#pragma unroll
        for (int rs = 0; rs < 8; rs++) {
            const float* yc = yr + rs * (YROWS * YPITCH);
            int cg = chbase + rs;                 // global channel being consumed

            float4 xa = (cg & 1) ? xq1 : xq0;
            // refill slot with channel cg+2 (clamped reload at tail)
            {
                float4 nv = *(const float4*)xld;
                if (cg & 1) xq1 = nv; else xq0 = nv;
                if (cg < 125) xld += HW_;
            }

            u64 xe0 = pack2(xa.x, xa.y);
            u64 xe1 = pack2(xa.z, xa.w);

            float4 y0 = *(const float4*)(yc);
            u64 e0 = pack2(y0.x, y0.y);
            u64 e1 = pack2(y0.z, y0.w);
            u64 o0 = pack2(y0.y, y0.z);
            acc[0][0] = ffma2u(xe0, e0, acc[0][0]);
            acc[2][0] = ffma2u(xe0, e1, acc[2][0]);
            acc[0][1] = ffma2u(xe1, e1, acc[0][1]);
            acc[1][0] = ffma2u(xe0, o0, acc[1][0]);

            float4 y1 = *(const float4*)(yc + 4);
            u64 o1 = pack2(y0.w, y1.x);
            u64 e2 = pack2(y1.x, y1.y);
            u64 e3 = pack2(y1.z, y1.w);
            u64 o2 = pack2(y1.y, y1.z);
            acc[3][0] = ffma2u(xe0, o1, acc[3][0]);
            acc[1][1] = ffma2u(xe1, o1, acc[1][1]);
            acc[4][0] = ffma2u(xe0, e2, acc[4][0]);
            acc[2][1] = ffma2u(xe1, e2, acc[2][1]);
            acc[6][0] = ffma2u(xe0, e3, acc[6][0]);
            acc[4][1] = ffma2u(xe1, e3, acc[4][1]);
            acc[5][0] = ffma2u(xe0, o2, acc[5][0]);
            acc[3][1] = ffma2u(xe1, o2, acc[3][1]);

            float4 y2 = *(const float4*)(yc + 8);
            u64 o3 = pack2(y1.w, y2.x);
            u64 e4 = pack2(y2.x, y2.y);
            u64 e5 = pack2(y2.z, y2.w);
            u64 o4 = pack2(y2.y, y2.z);
            acc[7][0] = ffma2u(xe0, o3, acc[7][0]);
            acc[5][1] = ffma2u(xe1, o3, acc[5][1]);
            acc[8][0] = ffma2u(xe0, e4, acc[8][0]);
            acc[6][1] = ffma2u(xe1, e4, acc[6][1]);
            acc[8][1] = ffma2u(xe1, e5, acc[8][1]);
            acc[7][1] = ffma2u(xe1, o4, acc[7][1]);
        }
    };

    // prefill 2 stages (4 groups)
    prefetchA(0, 0); prefetchB(0, 0);
    prefetchA(1, 1); prefetchB(1, 1);

    for (int s = 0; s < NSTAGE; s++) {
        // retire stage-s groups: issued 2 stages ago except at tail
        if (s < NSTAGE - 1) cp_wait<2>();
        else                cp_wait<0>();
        __syncthreads();          // publish stage s; buf (s+2)%3 free
        const int buf = s % 3;
        const int nbuf = (s + 2) % 3;
        if (s + 2 < NSTAGE) prefetchA(s + 2, nbuf);
        compute_half(buf, 0, s * CH);
        if (s + 2 < NSTAGE) prefetchB(s + 2, nbuf);
        compute_half(buf, 1, s * CH + 8);
    }

    // ---- epilogue: 9 float4 stores ----
    const float inv_c = 1.0f / (float)C_;
    const int hrow = h0 + hr;
#pragma unroll
    for (int j = 0; j < K_; j++) {
        int o = io * K_ + j;
        float* op = out + (((size_t)b * NOFF + o) * H_ + hrow) * W_ + w0 + wg * PXT;
        float2 v0 = unpack2(acc[j][0]);
        float2 v1 = unpack2(acc[j][1]);
        *(float4*)op = make_float4(v0.x * inv_c, v0.y * inv_c,
                                   v1.x * inv_c, v1.y * inv_c);
    }
}

extern "C" void kernel_launch(void* const* d_in, const int* in_sizes, int n_in,
                              void* d_out, int out_size) {
    const float* x = (const float*)d_in[0];
    const float* y = (const float*)d_in[1];
    float* out = (float*)d_out;

    static bool attr_set = false;
    if (!attr_set) {
        cudaFuncSetAttribute(corr_kernel,
                             cudaFuncAttributeMaxDynamicSharedMemorySize,
                             SMEM_BYTES);
        attr_set = true;
    }

    dim3 grid(W_ / TW, H_ / TH, B_);   // 12 x 24 x 4 = 1152 blocks
    corr_kernel<<<grid, NTHREADS, SMEM_BYTES>>>(x, y, out);
}

// round 17
// speedup vs baseline: 1.4473x; 1.4473x over previous
#include <cuda_runtime.h>
#include <cstdint>

// Problem constants
#define B_   4
#define C_   128
#define H_   192
#define W_   192
#define HW_  (H_*W_)
#define K_   9
#define PAD  4
#define NOFF 81

// Tiling (occ-3 operating point, CH=16 -> 8 barriers)
#define TH   8
#define TW   16
#define PXT  4
#define NTHREADS 288           // 4 wg * 9 io * 8 hr
#define CH   16
#define NSTAGE 8
#define YROWS 16               // TH + 2*PAD
#define YPITCH 48              // ≡16 mod 32 -> conflict-free; 2 channels share one row
#define XPITCH 16
#define XSZ  (CH*TH*XPITCH)    // 2048 floats
#define YSZ  (8*YROWS*YPITCH)  // 6144 floats (8 rowsets x 2 col-halves)
#define BUFSZ (XSZ + YSZ)      // 8192 floats
#define SMEM_BYTES (2*BUFSZ*4) // 65536 bytes (<= 76K occ-3 budget)

typedef unsigned long long u64;

__device__ __forceinline__ u64 pack2(float lo, float hi) {
    u64 r;
    asm("mov.b64 %0, {%1, %2};" : "=l"(r) : "f"(lo), "f"(hi));
    return r;
}
__device__ __forceinline__ u64 ffma2u(u64 a, u64 b, u64 c) {
    u64 d;
    asm("fma.rn.f32x2 %0, %1, %2, %3;" : "=l"(d) : "l"(a), "l"(b), "l"(c));
    return d;
}
__device__ __forceinline__ float2 unpack2(u64 v) {
    float2 r;
    asm("mov.b64 {%0, %1}, %2;" : "=f"(r.x), "=f"(r.y) : "l"(v));
    return r;
}

__device__ __forceinline__ void cp16(uint32_t dst, const void* src, int srcsize) {
    asm volatile("cp.async.cg.shared.global [%0], [%1], 16, %2;"
                 :: "r"(dst), "l"(src), "r"(srcsize));
}
__device__ __forceinline__ void cp_commit() {
    asm volatile("cp.async.commit_group;");
}
template <int N>
__device__ __forceinline__ void cp_wait() {
    asm volatile("cp.async.wait_group %0;" :: "n"(N));
}

__global__ void __launch_bounds__(NTHREADS, 3)
corr_kernel(const float* __restrict__ x,
            const float* __restrict__ y,
            float* __restrict__ out) {
    extern __shared__ float sm[];

    const int tid = threadIdx.x;
    const int wg  = tid & 3;
    const int io  = (tid >> 2) % 9;
    const int hr  = tid / 36;

    const int b  = blockIdx.z;
    const int h0 = blockIdx.y * TH;
    const int w0 = blockIdx.x * TW;

    const float* xb = x + (size_t)b * C_ * HW_;
    const float* yb = y + (size_t)b * C_ * HW_;

    const uint32_t sm_base = (uint32_t)__cvta_generic_to_shared(sm);

    // y chunk: chunk 0..1535 -> channel c (0..15) rowset (c&7), col-half (c>>3)
    auto y_chunk = [&](int c0, uint32_t ys_base, int chunk) {
        int t = chunk / 6;               // (c, r)
        int q = chunk - 6 * t;
        int c = t >> 4;
        int r = t & 15;
        int gh = h0 + r - PAD;
        int gw = w0 - 4 + q * 4;
        bool ok = ((unsigned)gh < (unsigned)H_) &&
                  ((unsigned)gw <= (unsigned)(W_ - 4));
        const float* src = ok ? yb + (size_t)(c0 + c) * HW_ + gh * W_ + gw : yb;
        uint32_t dst = ys_base +
            (uint32_t)(((c & 7) * YROWS + r) * YPITCH + (c >> 3) * 24 + q * 4) * 4u;
        cp16(dst, src, ok ? 16 : 0);
    };
    auto x_tile = [&](int c0, uint32_t base, int idx) {
        int c  = idx >> 5;               // 0..15
        int r  = (idx >> 2) & 7;
        int c4 = idx & 3;
        const float* src = xb + (size_t)(c0 + c) * HW_ + (h0 + r) * W_ + w0 + c4 * 4;
        cp16(base + (uint32_t)((c * TH + r) * XPITCH + c4 * 4) * 4u, src, 16);
    };

    // part A: x (512 f4) + y chunks 0..511   (4 cp / thread)
    auto prefetchA = [&](int c0, int buf) {
        const uint32_t base = sm_base + (uint32_t)(buf * BUFSZ) * 4u;
        if (tid < 256) {
            x_tile(c0, base, tid);
            x_tile(c0, base, tid + 256);
            y_chunk(c0, base + (uint32_t)XSZ * 4u, tid);
            y_chunk(c0, base + (uint32_t)XSZ * 4u, tid + 256);
        }
        cp_commit();
    };
    // part B: y chunks 512..1535   (4 cp / thread)
    auto prefetchB = [&](int c0, int buf) {
        const uint32_t base = sm_base + (uint32_t)(buf * BUFSZ) * 4u;
        if (tid < 256) {
            y_chunk(c0, base + (uint32_t)XSZ * 4u, tid + 512);
            y_chunk(c0, base + (uint32_t)XSZ * 4u, tid + 768);
            y_chunk(c0, base + (uint32_t)XSZ * 4u, tid + 1024);
            y_chunk(c0, base + (uint32_t)XSZ * 4u, tid + 1280);
        }
        cp_commit();
    };

    // accumulators: acc[j][q], pixel pair (2q, 2q+1); 18 u64 = 36 regs
    u64 acc[K_][2];
#pragma unroll
    for (int j = 0; j < K_; j++) { acc[j][0] = 0ull; acc[j][1] = 0ull; }

    // one quarter = 4 channels: qt -> col-half (qt>>1), rowsets (qt&1)*4 ..+3
    auto compute_quarter = [&](int buf, int qt) {
        const float* xp = sm + buf * BUFSZ + (qt * 4 * TH + hr) * XPITCH + wg * PXT;
        const float* yr = sm + buf * BUFSZ + XSZ
                          + ((qt & 1) * 4 * YROWS + hr + io) * YPITCH
                          + (qt >> 1) * 24 + wg * PXT;
#pragma unroll
        for (int c = 0; c < 4; c++) {
            const float* xc = xp + c * (TH * XPITCH);
            const float* yc = yr + c * (YROWS * YPITCH);

            float4 xa = *(const float4*)xc;
            u64 xe0 = pack2(xa.x, xa.y);
            u64 xe1 = pack2(xa.z, xa.w);

            float4 y0 = *(const float4*)(yc);
            u64 e0 = pack2(y0.x, y0.y);
            u64 e1 = pack2(y0.z, y0.w);
            u64 o0 = pack2(y0.y, y0.z);
            acc[0][0] = ffma2u(xe0, e0, acc[0][0]);
            acc[2][0] = ffma2u(xe0, e1, acc[2][0]);
            acc[0][1] = ffma2u(xe1, e1, acc[0][1]);
            acc[1][0] = ffma2u(xe0, o0, acc[1][0]);

            float4 y1 = *(const float4*)(yc + 4);
            u64 o1 = pack2(y0.w, y1.x);
            u64 e2 = pack2(y1.x, y1.y);
            u64 e3 = pack2(y1.z, y1.w);
            u64 o2 = pack2(y1.y, y1.z);
            acc[3][0] = ffma2u(xe0, o1, acc[3][0]);
            acc[1][1] = ffma2u(xe1, o1, acc[1][1]);
            acc[4][0] = ffma2u(xe0, e2, acc[4][0]);
            acc[2][1] = ffma2u(xe1, e2, acc[2][1]);
            acc[6][0] = ffma2u(xe0, e3, acc[6][0]);
            acc[4][1] = ffma2u(xe1, e3, acc[4][1]);
            acc[5][0] = ffma2u(xe0, o2, acc[5][0]);
            acc[3][1] = ffma2u(xe1, o2, acc[3][1]);

            float4 y2 = *(const float4*)(yc + 8);
            u64 o3 = pack2(y1.w, y2.x);
            u64 e4 = pack2(y2.x, y2.y);
            u64 e5 = pack2(y2.z, y2.w);
            u64 o4 = pack2(y2.y, y2.z);
            acc[7][0] = ffma2u(xe0, o3, acc[7][0]);
            acc[5][1] = ffma2u(xe1, o3, acc[5][1]);
            acc[8][0] = ffma2u(xe0, e4, acc[8][0]);
            acc[6][1] = ffma2u(xe1, e4, acc[6][1]);
            acc[8][1] = ffma2u(xe1, e5, acc[8][1]);
            acc[7][1] = ffma2u(xe1, o4, acc[7][1]);
        }
    };

    prefetchA(0, 0);
    prefetchB(0, 0);

    for (int s = 0; s < NSTAGE; s += 2) {
        // ---- stage s (buf 0) ----
        cp_wait<0>();
        __syncthreads();
        prefetchA((s + 1) * CH, 1);
        compute_quarter(0, 0);
        prefetchB((s + 1) * CH, 1);   // issued one quarter earlier: 3/4-stage slack
        compute_quarter(0, 1);
        compute_quarter(0, 2);
        compute_quarter(0, 3);

        // ---- stage s+1 (buf 1) ----
        cp_wait<0>();
        __syncthreads();
        if (s + 2 < NSTAGE) prefetchA((s + 2) * CH, 0);
        compute_quarter(1, 0);
        if (s + 2 < NSTAGE) prefetchB((s + 2) * CH, 0);
        compute_quarter(1, 1);
        compute_quarter(1, 2);
        compute_quarter(1, 3);
    }

    // ---- epilogue: 9 float4 stores ----
    const float inv_c = 1.0f / (float)C_;
    const int hrow = h0 + hr;
#pragma unroll
    for (int j = 0; j < K_; j++) {
        int o = io * K_ + j;
        float* op = out + (((size_t)b * NOFF + o) * H_ + hrow) * W_ + w0 + wg * PXT;
        float2 v0 = unpack2(acc[j][0]);
        float2 v1 = unpack2(acc[j][1]);
        *(float4*)op = make_float4(v0.x * inv_c, v0.y * inv_c,
                                   v1.x * inv_c, v1.y * inv_c);
    }
}

extern "C" void kernel_launch(void* const* d_in, const int* in_sizes, int n_in,
                              void* d_out, int out_size) {
    const float* x = (const float*)d_in[0];
    const float* y = (const float*)d_in[1];
    float* out = (float*)d_out;

    static bool attr_set = false;
    if (!attr_set) {
        cudaFuncSetAttribute(corr_kernel,
                             cudaFuncAttributeMaxDynamicSharedMemorySize,
                             SMEM_BYTES);
        attr_set = true;
    }

    dim3 grid(W_ / TW, H_ / TH, B_);   // 12 x 24 x 4 = 1152 blocks
    corr_kernel<<<grid, NTHREADS, SMEM_BYTES>>>(x, y, out);
}